// round 3
// baseline (speedup 1.0000x reference)
#include <cuda_runtime.h>
#include <cuda_bf16.h>
#include <math.h>

// InnerCos: mean over rows of clamp(1 - cos_sim(x_i, centers[label_i]))
// x: [N, 256] f32, label: [N] i32, centers: [C, 256] f32 -> scalar f32

#define D_DIM 256
#define THREADS 256               // 8 warps
#define NW (THREADS / 32)
#define ITERS 32                  // rows per warp
#define ROWS_PER_BLOCK (NW * ITERS)   // 256

// Pre-normalized centers (c / ||c||), C <= 256
__device__ float g_cnorm[256 * D_DIM];

// ---- Prologue: one warp per center, normalize into g_cnorm ----
__global__ void center_norm_kernel(const float* __restrict__ cen, int C)
{
    const int c    = blockIdx.x;
    const int lane = threadIdx.x;
    const float4* row = reinterpret_cast<const float4*>(cen + (size_t)c * D_DIM);
    float4 v0 = __ldg(row + lane);
    float4 v1 = __ldg(row + lane + 32);
    float s = v0.x*v0.x + v0.y*v0.y + v0.z*v0.z + v0.w*v0.w
            + v1.x*v1.x + v1.y*v1.y + v1.z*v1.z + v1.w*v1.w;
    #pragma unroll
    for (int o = 16; o > 0; o >>= 1)
        s += __shfl_xor_sync(0xffffffffu, s, o);
    float inv = rsqrtf(fmaxf(s, 1e-30f));
    v0.x *= inv; v0.y *= inv; v0.z *= inv; v0.w *= inv;
    v1.x *= inv; v1.y *= inv; v1.z *= inv; v1.w *= inv;
    float4* dst = reinterpret_cast<float4*>(g_cnorm + (size_t)c * D_DIM);
    dst[lane] = v0;
    dst[lane + 32] = v1;
}

// ---- Main: warp per row, label prefetch, normalized centers from L1 ----
__global__ void __launch_bounds__(THREADS, 6)
inner_cos_kernel(const float* __restrict__ x,
                 const int* __restrict__ lab,
                 float* __restrict__ out,
                 int N, float invN)
{
    const int tid  = threadIdx.x;
    const int lane = tid & 31;
    const int warp = tid >> 5;

    float acc = 0.0f;   // valid on lane 0 only
    const int row0 = blockIdx.x * ROWS_PER_BLOCK + warp;

    // prefetch first label
    int r  = row0;
    int lb = (r < N) ? __ldg(lab + r) : 0;

    #pragma unroll 4
    for (int it = 0; it < ITERS; ++it) {
        const int r_cur  = r;
        const int lb_cur = lb;
        const bool v     = r_cur < N;

        // prefetch next label (breaks lab->center dependency for next iter)
        r = row0 + (it + 1) * NW;
        if (it + 1 < ITERS && r < N) lb = __ldg(lab + r);

        if (v) {
            // issue all 4 wide loads back-to-back (x from DRAM, c from L1)
            const float4* xr = reinterpret_cast<const float4*>(x + (size_t)r_cur * D_DIM);
            const float4* cr = reinterpret_cast<const float4*>(g_cnorm + (size_t)lb_cur * D_DIM);
            float4 a0 = __ldg(xr + lane);
            float4 a1 = __ldg(xr + lane + 32);
            float4 c0 = cr[lane];
            float4 c1 = cr[lane + 32];

            float dot = a0.x*c0.x + a0.y*c0.y + a0.z*c0.z + a0.w*c0.w
                      + a1.x*c1.x + a1.y*c1.y + a1.z*c1.z + a1.w*c1.w;
            float nx2 = a0.x*a0.x + a0.y*a0.y + a0.z*a0.z + a0.w*a0.w
                      + a1.x*a1.x + a1.y*a1.y + a1.z*a1.z + a1.w*a1.w;

            #pragma unroll
            for (int o = 16; o > 0; o >>= 1) {
                dot += __shfl_xor_sync(0xffffffffu, dot, o);
                nx2 += __shfl_xor_sync(0xffffffffu, nx2, o);
            }

            if (lane == 0) {
                float cos = dot * rsqrtf(fmaxf(nx2, 1e-30f));
                acc += fminf(fmaxf(1.0f - cos, 1e-12f), 1e12f);
            }
        }
    }

    // ---- Block reduction + single atomic per block ----
    __shared__ float wsum[NW];
    if (lane == 0) wsum[warp] = acc;
    __syncthreads();
    if (tid == 0) {
        float s = 0.0f;
        #pragma unroll
        for (int i = 0; i < NW; ++i) s += wsum[i];
        atomicAdd(out, s * invN);
    }
}

extern "C" void kernel_launch(void* const* d_in, const int* in_sizes, int n_in,
                              void* d_out, int out_size)
{
    const float* x   = (const float*)d_in[0];   // ref_emb [N, 256]
    const int*   lab = (const int*)d_in[1];     // ref_label [N]
    const float* cen = (const float*)d_in[2];   // centers [C, 256]
    float* out = (float*)d_out;

    const int N = in_sizes[1];
    const int C = in_sizes[2] / D_DIM;

    cudaMemsetAsync(d_out, 0, sizeof(float), 0);

    center_norm_kernel<<<C, 32>>>(cen, C);

    const int blocks = (N + ROWS_PER_BLOCK - 1) / ROWS_PER_BLOCK;
    inner_cos_kernel<<<blocks, THREADS>>>(x, lab, out, N, 1.0f / (float)N);
}

// round 4
// speedup vs baseline: 1.2547x; 1.2547x over previous
#include <cuda_runtime.h>
#include <cuda_bf16.h>
#include <math.h>

// InnerCos: mean over rows of clamp(1 - cos_sim(x_i, centers[label_i]))
// x: [N, 256] f32, label: [N] i32, centers: [C, 256] f32 -> scalar f32

#define D_DIM 256
#define THREADS 256               // 8 warps
#define NW (THREADS / 32)
#define ROWS_PER_WARP_ITER 4      // 8 lanes per row
#define ROWS_PER_BLOCK 256
#define GROUPS (ROWS_PER_BLOCK / (NW * ROWS_PER_WARP_ITER))   // 8

// Pre-normalized centers (c / ||c||), C <= 256
__device__ float g_cnorm[256 * D_DIM];

// ---- Prologue: one warp per center, normalize into g_cnorm ----
__global__ void center_norm_kernel(const float* __restrict__ cen, int C)
{
    const int c    = blockIdx.x;
    const int lane = threadIdx.x;
    const float4* row = reinterpret_cast<const float4*>(cen + (size_t)c * D_DIM);
    float4 v0 = __ldg(row + lane);
    float4 v1 = __ldg(row + lane + 32);
    float s = v0.x*v0.x + v0.y*v0.y + v0.z*v0.z + v0.w*v0.w
            + v1.x*v1.x + v1.y*v1.y + v1.z*v1.z + v1.w*v1.w;
    #pragma unroll
    for (int o = 16; o > 0; o >>= 1)
        s += __shfl_xor_sync(0xffffffffu, s, o);
    float inv = rsqrtf(fmaxf(s, 1e-30f));
    v0.x *= inv; v0.y *= inv; v0.z *= inv; v0.w *= inv;
    v1.x *= inv; v1.y *= inv; v1.z *= inv; v1.w *= inv;
    float4* dst = reinterpret_cast<float4*>(g_cnorm + (size_t)c * D_DIM);
    dst[lane] = v0;
    dst[lane + 32] = v1;
}

// ---- Main: 8 lanes per row, 4 rows per warp, 8 batched LDG.128 per warp ----
__global__ void __launch_bounds__(THREADS, 4)
inner_cos_kernel(const float* __restrict__ x,
                 const int* __restrict__ lab,
                 float* __restrict__ out,
                 int N, float invN)
{
    const int tid  = threadIdx.x;
    const int lane = tid & 31;
    const int warp = tid >> 5;
    const int sub  = lane >> 3;   // which of the warp's 4 rows
    const int sl   = lane & 7;    // position within row (owns 8 float4)

    // this lane's row for group-iteration `it`:
    //   rbase + it * (NW * ROWS_PER_WARP_ITER)
    const int rbase = blockIdx.x * ROWS_PER_BLOCK
                    + warp * ROWS_PER_WARP_ITER + sub;

    float acc = 0.0f;

    // prefetch first label
    int r  = rbase;
    int lb = (r < N) ? __ldg(lab + r) : 0;

    #pragma unroll
    for (int it = 0; it < GROUPS; ++it) {
        const int r_cur  = r;
        const int lb_cur = lb;
        const bool v     = r_cur < N;

        // prefetch next group's label (breaks lab->center dependency)
        r = rbase + (it + 1) * (NW * ROWS_PER_WARP_ITER);
        if (it + 1 < GROUPS && r < N) lb = __ldg(lab + r);

        if (v) {
            const float4* xr = reinterpret_cast<const float4*>(x + (size_t)r_cur * D_DIM);
            const float4* cr = reinterpret_cast<const float4*>(g_cnorm + (size_t)lb_cur * D_DIM);

            // front-batch 8 independent DRAM loads (4 KB in flight per warp)
            float4 a[8];
            #pragma unroll
            for (int j = 0; j < 8; ++j)
                a[j] = __ldg(xr + sl + 8 * j);

            float dot = 0.0f, nx2 = 0.0f;
            #pragma unroll
            for (int j = 0; j < 8; ++j) {
                float4 c = cr[sl + 8 * j];   // L1 hit
                dot = fmaf(a[j].x, c.x, fmaf(a[j].y, c.y,
                      fmaf(a[j].z, c.z, fmaf(a[j].w, c.w, dot))));
                nx2 = fmaf(a[j].x, a[j].x, fmaf(a[j].y, a[j].y,
                      fmaf(a[j].z, a[j].z, fmaf(a[j].w, a[j].w, nx2))));
            }

            // reduce within the 8-lane group: 3 butterfly steps
            #pragma unroll
            for (int o = 4; o > 0; o >>= 1) {
                dot += __shfl_xor_sync(0xffffffffu, dot, o);
                nx2 += __shfl_xor_sync(0xffffffffu, nx2, o);
            }

            if (sl == 0) {
                float cos = dot * rsqrtf(fmaxf(nx2, 1e-30f));
                acc += fminf(fmaxf(1.0f - cos, 1e-12f), 1e12f);
            }
        }
    }

    // ---- full warp reduce of acc (nonzero only on sl==0 lanes) ----
    #pragma unroll
    for (int o = 16; o > 0; o >>= 1)
        acc += __shfl_xor_sync(0xffffffffu, acc, o);

    __shared__ float wsum[NW];
    if (lane == 0) wsum[warp] = acc;
    __syncthreads();
    if (tid == 0) {
        float s = 0.0f;
        #pragma unroll
        for (int i = 0; i < NW; ++i) s += wsum[i];
        atomicAdd(out, s * invN);
    }
}

extern "C" void kernel_launch(void* const* d_in, const int* in_sizes, int n_in,
                              void* d_out, int out_size)
{
    const float* x   = (const float*)d_in[0];   // ref_emb [N, 256]
    const int*   lab = (const int*)d_in[1];     // ref_label [N]
    const float* cen = (const float*)d_in[2];   // centers [C, 256]
    float* out = (float*)d_out;

    const int N = in_sizes[1];
    const int C = in_sizes[2] / D_DIM;

    cudaMemsetAsync(d_out, 0, sizeof(float), 0);

    center_norm_kernel<<<C, 32>>>(cen, C);

    const int blocks = (N + ROWS_PER_BLOCK - 1) / ROWS_PER_BLOCK;
    inner_cos_kernel<<<blocks, THREADS>>>(x, lab, out, N, 1.0f / (float)N);
}